// round 6
// baseline (speedup 1.0000x reference)
#include <cuda_runtime.h>
#include <math.h>
#include <float.h>
#include <stdint.h>

#define NN 32768
#define MM 1024
#define DD 128

// ---------------- device scratch (static: no allocation allowed) ------------
static __device__ float  g_logits[(size_t)NN * MM];  // 134 MB: logits, then encodings (in place)
static __device__ float  g_x2[NN];
static __device__ float  g_e2[MM];
static __device__ float  g_prec;
static __device__ double g_ent_part[256];
static __device__ double g_sq_part[256];
static __device__ int    g_counts[MM];

// ---------------- init: precision, zero accumulators ------------------------
__global__ void k_init(const float* __restrict__ lvq) {
    int t = threadIdx.x;
    if (t == 0) g_prec = expf(-lvq[0]);
    g_ent_part[t] = 0.0;
    for (int m = t; m < MM; m += 256) g_counts[m] = 0;
}

// ---------------- row squared norms (one warp per row of 128 floats) --------
__device__ __forceinline__ void rownorm_body(const float* __restrict__ src,
                                             float* __restrict__ dst, int rows) {
    int gw   = (blockIdx.x * blockDim.x + threadIdx.x) >> 5;
    int lane = threadIdx.x & 31;
    if (gw >= rows) return;
    float4 v = reinterpret_cast<const float4*>(src + (size_t)gw * DD)[lane];
    float s = v.x * v.x + v.y * v.y + v.z * v.z + v.w * v.w;
#pragma unroll
    for (int o = 16; o > 0; o >>= 1) s += __shfl_down_sync(0xffffffffu, s, o);
    if (lane == 0) dst[gw] = s;
}
__global__ void k_x2(const float* __restrict__ X) { rownorm_body(X, g_x2, NN); }
__global__ void k_e2(const float* __restrict__ E) { rownorm_body(E, g_e2, MM); }

// ---------------- GEMM1: logits = -0.5*prec*(x2 - 2*x@e^T + e2) -------------
// 128x128 tile, BK=16, 256 threads, 8x8 micro-tile per thread (NT gemm).
__global__ void __launch_bounds__(256, 2)
k_gemm1(const float* __restrict__ X, const float* __restrict__ E) {
    __shared__ float As[16][128];
    __shared__ float Bs[16][128];
    const int rowBase = blockIdx.y * 128;
    const int colBase = blockIdx.x * 128;
    const int t  = threadIdx.x;
    const int tx = t & 15, ty = t >> 4;

    float acc[8][8];
#pragma unroll
    for (int i = 0; i < 8; i++)
#pragma unroll
        for (int j = 0; j < 8; j++) acc[i][j] = 0.f;

    for (int k0 = 0; k0 < DD; k0 += 16) {
#pragma unroll
        for (int s = 0; s < 2; s++) {
            int q = t + s * 256;
            int row = q >> 2, kq = (q & 3) << 2;
            float4 va = *reinterpret_cast<const float4*>(X + (size_t)(rowBase + row) * DD + k0 + kq);
            As[kq + 0][row] = va.x; As[kq + 1][row] = va.y;
            As[kq + 2][row] = va.z; As[kq + 3][row] = va.w;
            float4 vb = *reinterpret_cast<const float4*>(E + (size_t)(colBase + row) * DD + k0 + kq);
            Bs[kq + 0][row] = vb.x; Bs[kq + 1][row] = vb.y;
            Bs[kq + 2][row] = vb.z; Bs[kq + 3][row] = vb.w;
        }
        __syncthreads();
#pragma unroll
        for (int kk = 0; kk < 16; kk++) {
            float a[8], b[8];
            *reinterpret_cast<float4*>(&a[0]) = *reinterpret_cast<const float4*>(&As[kk][ty * 8]);
            *reinterpret_cast<float4*>(&a[4]) = *reinterpret_cast<const float4*>(&As[kk][ty * 8 + 4]);
            *reinterpret_cast<float4*>(&b[0]) = *reinterpret_cast<const float4*>(&Bs[kk][tx * 8]);
            *reinterpret_cast<float4*>(&b[4]) = *reinterpret_cast<const float4*>(&Bs[kk][tx * 8 + 4]);
#pragma unroll
            for (int i = 0; i < 8; i++)
#pragma unroll
                for (int j = 0; j < 8; j++) acc[i][j] = fmaf(a[i], b[j], acc[i][j]);
        }
        __syncthreads();
    }

    const float prec = g_prec;
    float e2r[8];
#pragma unroll
    for (int j = 0; j < 8; j++) e2r[j] = g_e2[colBase + tx * 8 + j];
#pragma unroll
    for (int i = 0; i < 8; i++) {
        int n = rowBase + ty * 8 + i;
        float xn = g_x2[n];
        float o[8];
#pragma unroll
        for (int j = 0; j < 8; j++)
            o[j] = -0.5f * prec * (xn - 2.f * acc[i][j] + e2r[j]);
        float4* dst = reinterpret_cast<float4*>(g_logits + (size_t)n * MM + colBase + tx * 8);
        dst[0] = *reinterpret_cast<float4*>(&o[0]);
        dst[1] = *reinterpret_cast<float4*>(&o[4]);
    }
}

// ---------------- block reductions (256 threads) -----------------------------
__device__ __forceinline__ float blk_sum256(float v, float* sm) {
    int t = threadIdx.x;
#pragma unroll
    for (int o = 16; o > 0; o >>= 1) v += __shfl_down_sync(0xffffffffu, v, o);
    if ((t & 31) == 0) sm[t >> 5] = v;
    __syncthreads();
    if (t == 0) {
        float s = 0.f;
#pragma unroll
        for (int w = 0; w < 8; w++) s += sm[w];
        sm[0] = s;
    }
    __syncthreads();
    float r = sm[0];
    __syncthreads();
    return r;
}
__device__ __forceinline__ float blk_max256(float v, float* sm) {
    int t = threadIdx.x;
#pragma unroll
    for (int o = 16; o > 0; o >>= 1) v = fmaxf(v, __shfl_down_sync(0xffffffffu, v, o));
    if ((t & 31) == 0) sm[t >> 5] = v;
    __syncthreads();
    if (t == 0) {
        float s = sm[0];
#pragma unroll
        for (int w = 1; w < 8; w++) s = fmaxf(s, sm[w]);
        sm[0] = s;
    }
    __syncthreads();
    float r = sm[0];
    __syncthreads();
    return r;
}
__device__ __forceinline__ double blk_sum256d(double v, double* sm) {
    int t = threadIdx.x;
#pragma unroll
    for (int o = 16; o > 0; o >>= 1) v += __shfl_down_sync(0xffffffffu, v, o);
    if ((t & 31) == 0) sm[t >> 5] = v;
    __syncthreads();
    double r = 0.0;
    if (t == 0) {
#pragma unroll
        for (int w = 0; w < 8; w++) r += sm[w];
        sm[0] = r;
    }
    __syncthreads();
    r = sm[0];
    __syncthreads();
    return r;
}

// ---------------- per-row: argmax, gumbel softmax, entropy -------------------
__global__ void __launch_bounds__(256)
k_row(const float* __restrict__ U, float* __restrict__ out_idx, int write_idx) {
    __shared__ float sf[8];
    __shared__ int   si[8];
    const int n = blockIdx.x;
    const int t = threadIdx.x;
    float* row = g_logits + (size_t)n * MM;

    float4 l4 = *reinterpret_cast<const float4*>(row + t * 4);
    float4 u4 = *reinterpret_cast<const float4*>(U + (size_t)n * MM + t * 4);
    float l[4]  = {l4.x, l4.y, l4.z, l4.w};
    float uu[4] = {u4.x, u4.y, u4.z, u4.w};

    // argmax(logits) == argmin(distances); first-occurrence tie break
    float bv = l[0]; int bi = t * 4;
#pragma unroll
    for (int c = 1; c < 4; c++)
        if (l[c] > bv) { bv = l[c]; bi = t * 4 + c; }
#pragma unroll
    for (int o = 16; o > 0; o >>= 1) {
        float ov = __shfl_down_sync(0xffffffffu, bv, o);
        int   oi = __shfl_down_sync(0xffffffffu, bi, o);
        if (ov > bv || (ov == bv && oi < bi)) { bv = ov; bi = oi; }
    }
    if ((t & 31) == 0) { sf[t >> 5] = bv; si[t >> 5] = bi; }
    __syncthreads();
    if (t == 0) {
        float m = sf[0]; int ix = si[0];
#pragma unroll
        for (int w = 1; w < 8; w++)
            if (sf[w] > m || (sf[w] == m && si[w] < ix)) { m = sf[w]; ix = si[w]; }
        sf[0] = m; si[0] = ix;
    }
    __syncthreads();
    const float gmax = sf[0];
    if (t == 0) {
        int gi = si[0];
        if (write_idx) out_idx[n] = (float)gi;
        atomicAdd(&g_counts[gi], 1);
    }
    __syncthreads();

    // gumbel-softmax encodings (tau = 1), written back in place
    const float EPSF = 1.1920929e-07f;
    float p[4];
#pragma unroll
    for (int c = 0; c < 4; c++) {
        float uc = fminf(fmaxf(uu[c], EPSF), 1.0f - EPSF);
        p[c] = l[c] - logf(-logf(uc));   // logits + gumbel
    }
    float pm = fmaxf(fmaxf(p[0], p[1]), fmaxf(p[2], p[3]));
    pm = blk_max256(pm, sf);
    float es[4]; float esum = 0.f;
#pragma unroll
    for (int c = 0; c < 4; c++) { es[c] = expf(p[c] - pm); esum += es[c]; }
    esum = blk_sum256(esum, sf);
    float inv = 1.0f / esum;
    float4 enc = make_float4(es[0] * inv, es[1] * inv, es[2] * inv, es[3] * inv);
    *reinterpret_cast<float4*>(row + t * 4) = enc;

    // sum p*logp over the row = S2/S1 - log(S1), z = l - gmax
    float s1 = 0.f, s2 = 0.f;
#pragma unroll
    for (int c = 0; c < 4; c++) {
        float z = l[c] - gmax;
        float ez = expf(z);
        s1 += ez; s2 += ez * z;
    }
    s1 = blk_sum256(s1, sf);
    s2 = blk_sum256(s2, sf);
    if (t == 0) {
        double ent = (double)s2 / (double)s1 - log((double)s1);
        atomicAdd(&g_ent_part[n & 255], ent);
    }
}

// ---------------- GEMM2: quantized = enc @ e, fused sq-error ----------------
// 128 rows x 128 cols (full D), K=1024 in BK=16 chunks (NN gemm). grid = 256.
__global__ void __launch_bounds__(256, 2)
k_gemm2(const float* __restrict__ E, const float* __restrict__ X, float* __restrict__ Q) {
    __shared__ float As[16][128];
    __shared__ float Bs[16][128];
    const int rowBase = blockIdx.x * 128;
    const int t  = threadIdx.x;
    const int tx = t & 15, ty = t >> 4;

    float acc[8][8];
#pragma unroll
    for (int i = 0; i < 8; i++)
#pragma unroll
        for (int j = 0; j < 8; j++) acc[i][j] = 0.f;

    const float* A = g_logits;  // encodings
    for (int k0 = 0; k0 < MM; k0 += 16) {
#pragma unroll
        for (int s = 0; s < 2; s++) {
            int q = t + s * 256;
            int row = q >> 2, kq = (q & 3) << 2;
            float4 va = *reinterpret_cast<const float4*>(A + (size_t)(rowBase + row) * MM + k0 + kq);
            As[kq + 0][row] = va.x; As[kq + 1][row] = va.y;
            As[kq + 2][row] = va.z; As[kq + 3][row] = va.w;
            int bk = q >> 5, bd = (q & 31) << 2;
            float4 vb = *reinterpret_cast<const float4*>(E + (size_t)(k0 + bk) * DD + bd);
            *reinterpret_cast<float4*>(&Bs[bk][bd]) = vb;
        }
        __syncthreads();
#pragma unroll
        for (int kk = 0; kk < 16; kk++) {
            float a[8], b[8];
            *reinterpret_cast<float4*>(&a[0]) = *reinterpret_cast<const float4*>(&As[kk][ty * 8]);
            *reinterpret_cast<float4*>(&a[4]) = *reinterpret_cast<const float4*>(&As[kk][ty * 8 + 4]);
            *reinterpret_cast<float4*>(&b[0]) = *reinterpret_cast<const float4*>(&Bs[kk][tx * 8]);
            *reinterpret_cast<float4*>(&b[4]) = *reinterpret_cast<const float4*>(&Bs[kk][tx * 8 + 4]);
#pragma unroll
            for (int i = 0; i < 8; i++)
#pragma unroll
                for (int j = 0; j < 8; j++) acc[i][j] = fmaf(a[i], b[j], acc[i][j]);
        }
        __syncthreads();
    }

    float sq = 0.f;
#pragma unroll
    for (int i = 0; i < 8; i++) {
        int n = rowBase + ty * 8 + i;
        const float4* xr = reinterpret_cast<const float4*>(X + (size_t)n * DD + tx * 8);
        float4 x0 = xr[0], x1 = xr[1];
        float xv[8] = {x0.x, x0.y, x0.z, x0.w, x1.x, x1.y, x1.z, x1.w};
        float o[8];
#pragma unroll
        for (int j = 0; j < 8; j++) {
            o[j] = acc[i][j];
            float d = xv[j] - o[j];
            sq = fmaf(d, d, sq);
        }
        float4* dst = reinterpret_cast<float4*>(Q + (size_t)n * DD + tx * 8);
        dst[0] = *reinterpret_cast<float4*>(&o[0]);
        dst[1] = *reinterpret_cast<float4*>(&o[4]);
    }
    __shared__ float sm[8];
    float tot = blk_sum256(sq, sm);
    if (t == 0) g_sq_part[blockIdx.x] = (double)tot;
}

// ---------------- final scalars ---------------------------------------------
__global__ void k_final(float* __restrict__ out_tail, int do_write) {
    __shared__ double sd[8];
    int t = threadIdx.x;
    double ent = g_ent_part[t];
    double sq  = g_sq_part[t];
    double pp  = 0.0;
    for (int m = t; m < MM; m += 256) {
        double a = (double)g_counts[m] * (1.0 / (double)NN);
        pp += a * log(a + 1e-10);
    }
    double entS = blk_sum256d(ent, sd);
    double sqS  = blk_sum256d(sq, sd);
    double ppS  = blk_sum256d(pp, sd);
    if (t == 0 && do_write) {
        double prec = (double)g_prec;
        out_tail[0] = (float)(0.5 * prec * sqS + entS);  // loss
        out_tail[1] = (float)exp(-ppS);                  // perplexity
    }
}

// ---------------- launch -----------------------------------------------------
extern "C" void kernel_launch(void* const* d_in, const int* in_sizes, int n_in,
                              void* d_out, int out_size) {
    const float* x  = (const float*)d_in[0];  // (N, D)
    const float* e  = (const float*)d_in[1];  // (M, D)
    const float* lv = (const float*)d_in[2];  // (1,)
    const float* u  = (const float*)d_in[3];  // (N, M)

    float* out      = (float*)d_out;
    float* out_q    = out;                                  // N*D
    float* out_idx  = out + (size_t)NN * DD;                // N
    float* out_tail = out_idx + NN;                         // loss, perplexity
    int full = (out_size >= NN * DD + NN + 2) ? 1 : 0;

    k_init<<<1, 256>>>(lv);
    k_x2<<<NN / 8, 256>>>(x);
    k_e2<<<MM / 8, 256>>>(e);
    {
        dim3 g(MM / 128, NN / 128);
        k_gemm1<<<g, 256>>>(x, e);
    }
    k_row<<<NN, 256>>>(u, out_idx, full);
    k_gemm2<<<NN / 128, 256>>>(e, x, out_q);
    k_final<<<1, 256>>>(out_tail, full);
}